// round 3
// baseline (speedup 1.0000x reference)
#include <cuda_runtime.h>
#include <cuda_fp16.h>
#include <math.h>

#define BB 256
#define PP 256
#define NSTEP 31
#define VV 3433
#define HH 512
#define EE 300
#define CC 128
#define G3H 1536

// ---------------- scratch (device globals; no allocation) ----------------
__device__ __half g_fp16[(size_t)BB * PP * HH];   // feat_proj fp16: 64 MB
__device__ __half g_cf16[(size_t)BB * PP * CC];   // c_feats fp16: 16 MB
__device__ float g_tdt[BB * CC];
__device__ float g_h1a[BB * HH], g_h1b[BB * HH];
__device__ float g_h2a[BB * HH], g_h2b[BB * HH];
__device__ float g_tmp[BB * CC];
__device__ float g_s[BB * CC];
__device__ float g_gx[BB * G3H], g_gh0[BB * G3H], g_gh1[BB * G3H];
__device__ float g_u[BB * HH];
__device__ float g_att[BB * CC];

__device__ __forceinline__ float sigf(float x) {
    return 1.f / (1.f + __expf(-x));
}
__device__ __forceinline__ float tanh_fast(float x) {
    float e = __expf(-2.f * fabsf(x));
    float r = (1.f - e) / (1.f + e);
    return copysignf(r, x);
}

// ================= balanced 64x64 GEMM, 64 threads, TM=TN=8 ================
// out = act(A @ W^T + bias); A: 256(or M)xK lda, W: NxK ldw. M multiple of 64.
// act: 0 none, 1 relu. outHalf: write __half (outh) else float (out).
__global__ __launch_bounds__(64) void gemm64(
    int N, int K,
    const float* __restrict__ A, int lda,
    const float* __restrict__ W, int ldw,
    const float* __restrict__ bias,
    float* __restrict__ out, __half* __restrict__ outh, int ldc,
    int act)
{
    __shared__ float As[16][68];
    __shared__ float Ws[16][68];
    const int bn = blockIdx.x * 64, bm = blockIdx.y * 64;
    const int tid = threadIdx.x;
    const int tx = tid & 7, ty = tid >> 3;

    float acc[8][8];
#pragma unroll
    for (int i = 0; i < 8; i++)
#pragma unroll
        for (int j = 0; j < 8; j++) acc[i][j] = 0.f;

    for (int k0 = 0; k0 < K; k0 += 16) {
        // A tile: row = bm+tid, 16 k
        {
            const float* Ar = A + (size_t)(bm + tid) * lda + k0;
            if (k0 + 16 <= K) {
                float4 v0 = *(const float4*)(Ar);
                float4 v1 = *(const float4*)(Ar + 4);
                float4 v2 = *(const float4*)(Ar + 8);
                float4 v3 = *(const float4*)(Ar + 12);
                As[0][tid] = v0.x;  As[1][tid] = v0.y;  As[2][tid] = v0.z;  As[3][tid] = v0.w;
                As[4][tid] = v1.x;  As[5][tid] = v1.y;  As[6][tid] = v1.z;  As[7][tid] = v1.w;
                As[8][tid] = v2.x;  As[9][tid] = v2.y;  As[10][tid] = v2.z; As[11][tid] = v2.w;
                As[12][tid] = v3.x; As[13][tid] = v3.y; As[14][tid] = v3.z; As[15][tid] = v3.w;
            } else {
#pragma unroll
                for (int c = 0; c < 16; c++)
                    As[c][tid] = (k0 + c < K) ? Ar[c] : 0.f;
            }
        }
        // W tile: row n = bn+tid (guard n<N), 16 k
        {
            int n = bn + tid;
            if (n < N && k0 + 16 <= K) {
                const float* Wr = W + (size_t)n * ldw + k0;
                float4 v0 = *(const float4*)(Wr);
                float4 v1 = *(const float4*)(Wr + 4);
                float4 v2 = *(const float4*)(Wr + 8);
                float4 v3 = *(const float4*)(Wr + 12);
                Ws[0][tid] = v0.x;  Ws[1][tid] = v0.y;  Ws[2][tid] = v0.z;  Ws[3][tid] = v0.w;
                Ws[4][tid] = v1.x;  Ws[5][tid] = v1.y;  Ws[6][tid] = v1.z;  Ws[7][tid] = v1.w;
                Ws[8][tid] = v2.x;  Ws[9][tid] = v2.y;  Ws[10][tid] = v2.z; Ws[11][tid] = v2.w;
                Ws[12][tid] = v3.x; Ws[13][tid] = v3.y; Ws[14][tid] = v3.z; Ws[15][tid] = v3.w;
            } else {
                const float* Wr = W + (size_t)n * ldw + k0;
#pragma unroll
                for (int c = 0; c < 16; c++)
                    Ws[c][tid] = (n < N && k0 + c < K) ? Wr[c] : 0.f;
            }
        }
        __syncthreads();
#pragma unroll
        for (int kk = 0; kk < 16; kk++) {
            float4 a0 = *(const float4*)&As[kk][ty * 8];
            float4 a1 = *(const float4*)&As[kk][ty * 8 + 4];
            float4 w0 = *(const float4*)&Ws[kk][tx * 8];
            float4 w1 = *(const float4*)&Ws[kk][tx * 8 + 4];
            float a[8] = {a0.x, a0.y, a0.z, a0.w, a1.x, a1.y, a1.z, a1.w};
            float w[8] = {w0.x, w0.y, w0.z, w0.w, w1.x, w1.y, w1.z, w1.w};
#pragma unroll
            for (int i = 0; i < 8; i++)
#pragma unroll
                for (int j = 0; j < 8; j++)
                    acc[i][j] = fmaf(a[i], w[j], acc[i][j]);
        }
        __syncthreads();
    }
#pragma unroll
    for (int i = 0; i < 8; i++) {
        int m = bm + ty * 8 + i;
#pragma unroll
        for (int j = 0; j < 8; j++) {
            int n = bn + tx * 8 + j;
            if (n >= N) continue;
            float v = acc[i][j];
            if (bias) v += bias[n];
            if (act == 1) v = fmaxf(v, 0.f);
            if (outh) outh[(size_t)m * ldc + n] = __float2half(v);
            else      out[(size_t)m * ldc + n] = v;
        }
    }
}

// ====== dual-source GEMM + tanh: out = tanh(A1@W1^T + A2@W2^T [+ D]) ======
__global__ __launch_bounds__(64) void dual_gemm_tanh(
    const float* __restrict__ A1, int lda1, int K1, const float* __restrict__ W1,
    const float* __restrict__ A2, int lda2, int K2, const float* __restrict__ W2,
    const float* __restrict__ D, float* __restrict__ out)
{
    __shared__ float As[16][68];
    __shared__ float Ws[16][68];
    const int bn = blockIdx.x * 64, bm = blockIdx.y * 64;
    const int tid = threadIdx.x;
    const int tx = tid & 7, ty = tid >> 3;

    float acc[8][8];
#pragma unroll
    for (int i = 0; i < 8; i++)
#pragma unroll
        for (int j = 0; j < 8; j++) acc[i][j] = 0.f;

    for (int ph = 0; ph < 2; ph++) {
        const float* A = ph ? A2 : A1;
        const float* W = ph ? W2 : W1;
        const int lda = ph ? lda2 : lda1;
        const int K = ph ? K2 : K1;
        for (int k0 = 0; k0 < K; k0 += 16) {
            {
                const float* Ar = A + (size_t)(bm + tid) * lda + k0;
                const float* Wr = W + (size_t)(bn + tid) * K + k0;
                if (k0 + 16 <= K) {
                    float4 v0 = *(const float4*)(Ar);
                    float4 v1 = *(const float4*)(Ar + 4);
                    float4 v2 = *(const float4*)(Ar + 8);
                    float4 v3 = *(const float4*)(Ar + 12);
                    As[0][tid] = v0.x;  As[1][tid] = v0.y;  As[2][tid] = v0.z;  As[3][tid] = v0.w;
                    As[4][tid] = v1.x;  As[5][tid] = v1.y;  As[6][tid] = v1.z;  As[7][tid] = v1.w;
                    As[8][tid] = v2.x;  As[9][tid] = v2.y;  As[10][tid] = v2.z; As[11][tid] = v2.w;
                    As[12][tid] = v3.x; As[13][tid] = v3.y; As[14][tid] = v3.z; As[15][tid] = v3.w;
                    float4 u0 = *(const float4*)(Wr);
                    float4 u1 = *(const float4*)(Wr + 4);
                    float4 u2 = *(const float4*)(Wr + 8);
                    float4 u3 = *(const float4*)(Wr + 12);
                    Ws[0][tid] = u0.x;  Ws[1][tid] = u0.y;  Ws[2][tid] = u0.z;  Ws[3][tid] = u0.w;
                    Ws[4][tid] = u1.x;  Ws[5][tid] = u1.y;  Ws[6][tid] = u1.z;  Ws[7][tid] = u1.w;
                    Ws[8][tid] = u2.x;  Ws[9][tid] = u2.y;  Ws[10][tid] = u2.z; Ws[11][tid] = u2.w;
                    Ws[12][tid] = u3.x; Ws[13][tid] = u3.y; Ws[14][tid] = u3.z; Ws[15][tid] = u3.w;
                } else {
#pragma unroll
                    for (int c = 0; c < 16; c++) {
                        bool ok = (k0 + c < K);
                        As[c][tid] = ok ? Ar[c] : 0.f;
                        Ws[c][tid] = ok ? Wr[c] : 0.f;
                    }
                }
            }
            __syncthreads();
#pragma unroll
            for (int kk = 0; kk < 16; kk++) {
                float4 a0 = *(const float4*)&As[kk][ty * 8];
                float4 a1 = *(const float4*)&As[kk][ty * 8 + 4];
                float4 w0 = *(const float4*)&Ws[kk][tx * 8];
                float4 w1 = *(const float4*)&Ws[kk][tx * 8 + 4];
                float a[8] = {a0.x, a0.y, a0.z, a0.w, a1.x, a1.y, a1.z, a1.w};
                float w[8] = {w0.x, w0.y, w0.z, w0.w, w1.x, w1.y, w1.z, w1.w};
#pragma unroll
                for (int i = 0; i < 8; i++)
#pragma unroll
                    for (int j = 0; j < 8; j++)
                        acc[i][j] = fmaf(a[i], w[j], acc[i][j]);
            }
            __syncthreads();
        }
    }
#pragma unroll
    for (int i = 0; i < 8; i++) {
        int m = bm + ty * 8 + i;
#pragma unroll
        for (int j = 0; j < 8; j++) {
            int n = bn + tx * 8 + j;
            float v = acc[i][j];
            if (D) v += D[m * CC + n];
            out[(size_t)m * CC + n] = tanh_fast(v);
        }
    }
}

// ---- GRU pointwise: gates from gx(+bih) and gh0+gh1(+bhh), update h ----
__global__ __launch_bounds__(256) void gru_pw(
    const float* __restrict__ gx, const float* __restrict__ gh0,
    const float* __restrict__ gh1, const float* __restrict__ bhh,
    const float* __restrict__ hp, float* __restrict__ hn)
{
    int i = blockIdx.x * 256 + threadIdx.x;   // 0 .. B*H-1
    int b = i >> 9, j = i & 511;
    size_t base = (size_t)b * G3H;
    float gr = gx[base + j] + gh0[base + j] + gh1[base + j] + bhh[j];
    float gz = gx[base + 512 + j] + gh0[base + 512 + j] + gh1[base + 512 + j] + bhh[512 + j];
    float xn = gx[base + 1024 + j];
    float hg = gh0[base + 1024 + j] + gh1[base + 1024 + j] + bhh[1024 + j];
    float r = sigf(gr);
    float z = sigf(gz);
    float n = tanh_fast(xn + r * hg);
    hn[i] = (1.f - z) * n + z * hp[i];
}

// ---------------- fused attention (fp16 inputs) ----------------
__global__ __launch_bounds__(256) void attn_kernel(
    const __half* __restrict__ fp, const float* __restrict__ u,
    const float* __restrict__ wa, const __half* __restrict__ cf,
    float* __restrict__ att, float* __restrict__ outA, int t)
{
    const int b = blockIdx.x;
    const int tid = threadIdx.x;
    __shared__ float us[HH], was[HH], sc[PP], red[PP];

    for (int i = tid; i < HH; i += 256) {
        us[i] = u[(size_t)b * HH + i];
        was[i] = wa[i];
    }
    __syncthreads();

    const int w = tid >> 5, l = tid & 31;
    const __half* fpb = fp + (size_t)b * PP * HH;
    for (int p = w; p < PP; p += 8) {
        const __half2* row = (const __half2*)(fpb + (size_t)p * HH);
        float ssum = 0.f;
#pragma unroll
        for (int i = 0; i < 8; i++) {
            __half2 hv = row[l + i * 32];
            float2 f = __half22float2(hv);
            int h = 2 * (l + i * 32);
            ssum += was[h]     * tanh_fast(f.x + us[h]);
            ssum += was[h + 1] * tanh_fast(f.y + us[h + 1]);
        }
#pragma unroll
        for (int o = 16; o > 0; o >>= 1)
            ssum += __shfl_down_sync(0xffffffffu, ssum, o);
        if (l == 0) sc[p] = ssum;
    }
    __syncthreads();

    float v = sc[tid];
    red[tid] = v;
    __syncthreads();
    for (int st = 128; st > 0; st >>= 1) {
        if (tid < st) red[tid] = fmaxf(red[tid], red[tid + st]);
        __syncthreads();
    }
    float mx = red[0];
    __syncthreads();
    float e = __expf(v - mx);
    red[tid] = e;
    __syncthreads();
    for (int st = 128; st > 0; st >>= 1) {
        if (tid < st) red[tid] += red[tid + st];
        __syncthreads();
    }
    float mask = e * (1.f / red[0]);
    sc[tid] = mask;
    outA[((size_t)b * PP + tid) * NSTEP + t] = mask;
    __syncthreads();

    // attended[b,c] = sum_p mask[p] * cf16[b,p,c]
    const int c = tid & (CC - 1);
    const int half = tid >> 7;
    const __half* cfb = cf + (size_t)b * PP * CC;
    float a = 0.f;
    for (int p = half * 128; p < half * 128 + 128; p++)
        a += sc[p] * __half2float(cfb[(size_t)p * CC + c]);
    red[tid] = a;
    __syncthreads();
    if (tid < CC) att[(size_t)b * CC + tid] = red[tid] + red[tid + 128];
}

__global__ __launch_bounds__(256) void zero2(float* a, float* b) {
    int i = blockIdx.x * 256 + threadIdx.x;
    a[i] = 0.f;
    b[i] = 0.f;
}

__global__ __launch_bounds__(256) void cvt_half(
    const float* __restrict__ src, __half* __restrict__ dst, int n)
{
    int i = blockIdx.x * 256 + threadIdx.x;
    if (i < n) dst[i] = __float2half(src[i]);
}

// ---------------------------- host launcher -------------------------------
extern "C" void kernel_launch(void* const* d_in, const int* in_sizes, int n_in,
                              void* d_out, int out_size)
{
    const float* word_embs = (const float*)d_in[0];
    const float* t_feat    = (const float*)d_in[1];
    const float* c_feats   = (const float*)d_in[2];
    const int o = n_in - 20;
    const float* W_td1 = (const float*)d_in[o + 0];
    const float* W_td2 = (const float*)d_in[o + 1];
    const float* W_td3 = (const float*)d_in[o + 2];
    const float* W_td  = (const float*)d_in[o + 3];
    const float* W1_ih = (const float*)d_in[o + 4];
    const float* W1_hh = (const float*)d_in[o + 5];
    const float* b1_ih = (const float*)d_in[o + 6];
    const float* b1_hh = (const float*)d_in[o + 7];
    const float* W_feat = (const float*)d_in[o + 8];
    const float* W_hidd = (const float*)d_in[o + 9];
    const float* W_att  = (const float*)d_in[o + 10];
    const float* W_l1 = (const float*)d_in[o + 11];
    const float* W_l2 = (const float*)d_in[o + 12];
    const float* W_l  = (const float*)d_in[o + 13];
    const float* W2_ih = (const float*)d_in[o + 14];
    const float* W2_hh = (const float*)d_in[o + 15];
    const float* b2_ih = (const float*)d_in[o + 16];
    const float* b2_hh = (const float*)d_in[o + 17];
    const float* W_cls = (const float*)d_in[o + 18];
    const float* b_cls = (const float*)d_in[o + 19];

    float* out_lang = (float*)d_out;                         // (B, 31, V)
    float* out_att  = out_lang + (size_t)BB * NSTEP * VV;    // (B, P, 31)

    __half *fp16, *cf16;
    float *tdt, *h1a, *h1b, *h2a, *h2b, *tmp, *s, *gx, *gh0, *gh1, *u, *att;
    cudaGetSymbolAddress((void**)&fp16, g_fp16);
    cudaGetSymbolAddress((void**)&cf16, g_cf16);
    cudaGetSymbolAddress((void**)&tdt, g_tdt);
    cudaGetSymbolAddress((void**)&h1a, g_h1a);
    cudaGetSymbolAddress((void**)&h1b, g_h1b);
    cudaGetSymbolAddress((void**)&h2a, g_h2a);
    cudaGetSymbolAddress((void**)&h2b, g_h2b);
    cudaGetSymbolAddress((void**)&tmp, g_tmp);
    cudaGetSymbolAddress((void**)&s,   g_s);
    cudaGetSymbolAddress((void**)&gx,  g_gx);
    cudaGetSymbolAddress((void**)&gh0, g_gh0);
    cudaGetSymbolAddress((void**)&gh1, g_gh1);
    cudaGetSymbolAddress((void**)&u,   g_u);
    cudaGetSymbolAddress((void**)&att, g_att);

    // ---------- prologue ----------
    zero2<<<(BB * HH) / 256, 256>>>(h1a, h2a);
    cvt_half<<<(BB * PP * CC) / 256, 256>>>(c_feats, cf16, BB * PP * CC);
    // td_t = t_feat @ W_td2^T
    gemm64<<<dim3(CC / 64, BB / 64), 64>>>(
        CC, CC, t_feat, CC, W_td2, CC, nullptr, tdt, nullptr, CC, 0);
    // feat_proj = c_feats @ W_feat^T  -> fp16, (B*P) x H
    gemm64<<<dim3(HH / 64, (BB * PP) / 64), 64>>>(
        HH, CC, c_feats, CC, W_feat, CC, nullptr, nullptr, fp16, HH, 0);

    for (int t = 0; t < NSTEP; t++) {
        const float* h1p = (t & 1) ? h1b : h1a;
        float*       h1n = (t & 1) ? h1a : h1b;
        const float* h2p = (t & 1) ? h2b : h2a;
        float*       h2n = (t & 1) ? h2a : h2b;

        // tmp = tanh(x_t@W_td3^T + h2p@W_td1^T + tdt)
        dual_gemm_tanh<<<dim3(CC / 64, BB / 64), 64>>>(
            word_embs + (size_t)t * EE, 32 * EE, EE, W_td3,
            h2p, HH, HH, W_td1, tdt, tmp);
        // s = relu(tmp @ W_td^T)
        gemm64<<<dim3(CC / 64, BB / 64), 64>>>(
            CC, CC, tmp, CC, W_td, CC, nullptr, s, nullptr, CC, 1);
        // GRU 1: gx = s@W1_ih^T + b1_ih ; gh = h1p@W1_hh^T (split K)
        gemm64<<<dim3(G3H / 64, BB / 64), 64>>>(
            G3H, CC, s, CC, W1_ih, CC, b1_ih, gx, nullptr, G3H, 0);
        gemm64<<<dim3(G3H / 64, BB / 64), 64>>>(
            G3H, 256, h1p, HH, W1_hh, HH, nullptr, gh0, nullptr, G3H, 0);
        gemm64<<<dim3(G3H / 64, BB / 64), 64>>>(
            G3H, 256, h1p + 256, HH, W1_hh + 256, HH, nullptr, gh1, nullptr, G3H, 0);
        gru_pw<<<(BB * HH) / 256, 256>>>(gx, gh0, gh1, b1_hh, h1p, h1n);
        // u = h1 @ W_hidd^T
        gemm64<<<dim3(HH / 64, BB / 64), 64>>>(
            HH, HH, h1n, HH, W_hidd, HH, nullptr, u, nullptr, HH, 0);
        // attention
        attn_kernel<<<BB, 256>>>(fp16, u, W_att, cf16, att, out_att, t);
        // tmp = tanh(att@W_l1^T + h1@W_l2^T)
        dual_gemm_tanh<<<dim3(CC / 64, BB / 64), 64>>>(
            att, CC, CC, W_l1, h1n, HH, HH, W_l2, nullptr, tmp);
        // s = relu(tmp @ W_l^T)
        gemm64<<<dim3(CC / 64, BB / 64), 64>>>(
            CC, CC, tmp, CC, W_l, CC, nullptr, s, nullptr, CC, 1);
        // GRU 2
        gemm64<<<dim3(G3H / 64, BB / 64), 64>>>(
            G3H, CC, s, CC, W2_ih, CC, b2_ih, gx, nullptr, G3H, 0);
        gemm64<<<dim3(G3H / 64, BB / 64), 64>>>(
            G3H, 256, h2p, HH, W2_hh, HH, nullptr, gh0, nullptr, G3H, 0);
        gemm64<<<dim3(G3H / 64, BB / 64), 64>>>(
            G3H, 256, h2p + 256, HH, W2_hh + 256, HH, nullptr, gh1, nullptr, G3H, 0);
        gru_pw<<<(BB * HH) / 256, 256>>>(gx, gh0, gh1, b2_hh, h2p, h2n);
        // logits = h2 @ W_cls^T + b_cls
        gemm64<<<dim3((VV + 63) / 64, BB / 64), 64>>>(
            VV, HH, h2n, HH, W_cls, HH, b_cls,
            out_lang + (size_t)t * VV, nullptr, NSTEP * VV, 0);
    }
}

// round 6
// speedup vs baseline: 1.6830x; 1.6830x over previous
#include <cuda_runtime.h>
#include <cuda_fp16.h>
#include <math.h>

#define BB 256
#define PP 256
#define NSTEP 31
#define VV 3433
#define HH 512
#define EE 300
#define CC 128
#define G3H 1536

// ---------------- scratch (device globals; no allocation) ----------------
__device__ __half g_fp16[(size_t)BB * PP * HH];   // feat_proj fp16: 64 MB
__device__ __half g_cf16[(size_t)BB * PP * CC];   // c_feats fp16: 16 MB
__device__ float g_tdt[BB * CC];
__device__ float g_h1a[BB * HH], g_h1b[BB * HH];
__device__ float g_h2a[BB * HH], g_h2b[BB * HH];
__device__ float g_tmp[BB * CC];
__device__ float g_s[BB * CC];
__device__ float g_gx[BB * G3H], g_gh[BB * G3H];
__device__ float g_u[BB * HH];
__device__ float g_att[BB * CC];

__device__ __forceinline__ float sigf(float x) {
    return 1.f / (1.f + __expf(-x));
}
__device__ __forceinline__ float tanh_fast(float x) {
    float e = __expf(-2.f * fabsf(x));
    float r = (1.f - e) / (1.f + e);
    return copysignf(r, x);
}

// ============ 64x64 tile GEMM, 256 threads, TM=TN=4, reg-staged ============
// C[m,n] = epi( sum_k A(m,k)*W(n,k) + bias[n] (+ D[m,n]) )
// A(m,k): k<K1 from A1 (lda1), else A2 (lda2, k-K1). Same for W.
// EPI: 0 none, 1 relu, 2 tanh(+D), 3 write half
// M = gridDim.y*64 exactly (no M guard). N guarded.
template<int EPI>
__global__ __launch_bounds__(256) void gemmv(
    int N, int K1, int K2,
    const float* __restrict__ A1, int lda1,
    const float* __restrict__ A2, int lda2,
    const float* __restrict__ W1, int ldw1,
    const float* __restrict__ W2, int ldw2,
    const float* __restrict__ bias, const float* __restrict__ D,
    float* __restrict__ outF, __half* __restrict__ outH, int ldc)
{
    __shared__ float As[16][68];
    __shared__ float Ws[16][68];
    const int bn = blockIdx.x * 64, bm = blockIdx.y * 64;
    const int tid = threadIdx.x;
    const int tx = tid & 15, ty = tid >> 4;
    const int r = tid >> 2;            // 0..63 (tile row)
    const int ks = (tid & 3) << 2;     // 0,4,8,12
    const int KT = K1 + K2;
    const int ntiles = (KT + 15) >> 4;

    const int am = bm + r;
    const int wn = bn + r;
    const bool wvalid = (wn < N);

    float4 ra, rw;

    auto loadA = [&](int k0) {
        int k = k0 + ks;
        if (k + 4 <= K1) {
            ra = *(const float4*)(A1 + (size_t)am * lda1 + k);
        } else if (k >= K1 && k + 4 <= KT) {
            ra = *(const float4*)(A2 + (size_t)am * lda2 + (k - K1));
        } else {
            float t0[4];
#pragma unroll
            for (int j = 0; j < 4; j++) {
                int kk = k + j;
                t0[j] = (kk < K1) ? A1[(size_t)am * lda1 + kk]
                      : (kk < KT) ? A2[(size_t)am * lda2 + (kk - K1)] : 0.f;
            }
            ra = make_float4(t0[0], t0[1], t0[2], t0[3]);
        }
    };
    auto loadW = [&](int k0) {
        if (!wvalid) { rw = make_float4(0.f, 0.f, 0.f, 0.f); return; }
        int k = k0 + ks;
        if (k + 4 <= K1) {
            rw = *(const float4*)(W1 + (size_t)wn * ldw1 + k);
        } else if (k >= K1 && k + 4 <= KT) {
            rw = *(const float4*)(W2 + (size_t)wn * ldw2 + (k - K1));
        } else {
            float t0[4];
#pragma unroll
            for (int j = 0; j < 4; j++) {
                int kk = k + j;
                t0[j] = (kk < K1) ? W1[(size_t)wn * ldw1 + kk]
                      : (kk < KT) ? W2[(size_t)wn * ldw2 + (kk - K1)] : 0.f;
            }
            rw = make_float4(t0[0], t0[1], t0[2], t0[3]);
        }
    };

    float acc[4][4] = {};
    loadA(0); loadW(0);
    for (int it = 0; it < ntiles; ++it) {
        As[ks + 0][r] = ra.x; As[ks + 1][r] = ra.y;
        As[ks + 2][r] = ra.z; As[ks + 3][r] = ra.w;
        Ws[ks + 0][r] = rw.x; Ws[ks + 1][r] = rw.y;
        Ws[ks + 2][r] = rw.z; Ws[ks + 3][r] = rw.w;
        __syncthreads();
        if (it + 1 < ntiles) { loadA((it + 1) << 4); loadW((it + 1) << 4); }
#pragma unroll
        for (int kk = 0; kk < 16; kk++) {
            float4 a = *(const float4*)&As[kk][ty * 4];
            float4 w = *(const float4*)&Ws[kk][tx * 4];
            acc[0][0] = fmaf(a.x, w.x, acc[0][0]);
            acc[0][1] = fmaf(a.x, w.y, acc[0][1]);
            acc[0][2] = fmaf(a.x, w.z, acc[0][2]);
            acc[0][3] = fmaf(a.x, w.w, acc[0][3]);
            acc[1][0] = fmaf(a.y, w.x, acc[1][0]);
            acc[1][1] = fmaf(a.y, w.y, acc[1][1]);
            acc[1][2] = fmaf(a.y, w.z, acc[1][2]);
            acc[1][3] = fmaf(a.y, w.w, acc[1][3]);
            acc[2][0] = fmaf(a.z, w.x, acc[2][0]);
            acc[2][1] = fmaf(a.z, w.y, acc[2][1]);
            acc[2][2] = fmaf(a.z, w.z, acc[2][2]);
            acc[2][3] = fmaf(a.z, w.w, acc[2][3]);
            acc[3][0] = fmaf(a.w, w.x, acc[3][0]);
            acc[3][1] = fmaf(a.w, w.y, acc[3][1]);
            acc[3][2] = fmaf(a.w, w.z, acc[3][2]);
            acc[3][3] = fmaf(a.w, w.w, acc[3][3]);
        }
        __syncthreads();
    }

#pragma unroll
    for (int i = 0; i < 4; i++) {
        int m = bm + ty * 4 + i;
#pragma unroll
        for (int j = 0; j < 4; j++) {
            int n = bn + tx * 4 + j;
            if (n >= N) continue;
            float v = acc[i][j];
            if (bias) v += bias[n];
            if (EPI == 1) v = fmaxf(v, 0.f);
            if (EPI == 2) {
                if (D) v += D[(size_t)m * CC + n];
                v = tanh_fast(v);
            }
            if (EPI == 3) outH[(size_t)m * ldc + n] = __float2half(v);
            else          outF[(size_t)m * ldc + n] = v;
        }
    }
}

// ---- GRU pointwise: gates from gx(+bih) and gh(+bhh), update h ----
__global__ __launch_bounds__(256) void gru_pw(
    const float* __restrict__ gx, const float* __restrict__ gh,
    const float* __restrict__ hp, float* __restrict__ hn)
{
    int i = blockIdx.x * 256 + threadIdx.x;   // 0 .. B*H-1
    int b = i >> 9, j = i & 511;
    size_t base = (size_t)b * G3H;
    float r = sigf(gx[base + j] + gh[base + j]);
    float z = sigf(gx[base + 512 + j] + gh[base + 512 + j]);
    float n = tanh_fast(gx[base + 1024 + j] + r * gh[base + 1024 + j]);
    hn[i] = (1.f - z) * n + z * hp[i];
}

// ---------------- fused attention (fp16 inputs) ----------------
__global__ __launch_bounds__(256) void attn_kernel(
    const __half* __restrict__ fp, const float* __restrict__ u,
    const float* __restrict__ wa, const __half* __restrict__ cf,
    float* __restrict__ att, float* __restrict__ outA, int t)
{
    const int b = blockIdx.x;
    const int tid = threadIdx.x;
    __shared__ float us[HH], was[HH], sc[PP], red[PP];

    for (int i = tid; i < HH; i += 256) {
        us[i] = u[(size_t)b * HH + i];
        was[i] = wa[i];
    }
    __syncthreads();

    const int w = tid >> 5, l = tid & 31;
    const __half* fpb = fp + (size_t)b * PP * HH;
    for (int p = w; p < PP; p += 8) {
        const __half2* row = (const __half2*)(fpb + (size_t)p * HH);
        float ssum = 0.f;
#pragma unroll
        for (int i = 0; i < 8; i++) {
            __half2 hv = row[l + i * 32];
            float2 f = __half22float2(hv);
            int h = 2 * (l + i * 32);
            ssum += was[h]     * tanh_fast(f.x + us[h]);
            ssum += was[h + 1] * tanh_fast(f.y + us[h + 1]);
        }
#pragma unroll
        for (int o = 16; o > 0; o >>= 1)
            ssum += __shfl_down_sync(0xffffffffu, ssum, o);
        if (l == 0) sc[p] = ssum;
    }
    __syncthreads();

    float v = sc[tid];
    red[tid] = v;
    __syncthreads();
    for (int st = 128; st > 0; st >>= 1) {
        if (tid < st) red[tid] = fmaxf(red[tid], red[tid + st]);
        __syncthreads();
    }
    float mx = red[0];
    __syncthreads();
    float e = __expf(v - mx);
    red[tid] = e;
    __syncthreads();
    for (int st = 128; st > 0; st >>= 1) {
        if (tid < st) red[tid] += red[tid + st];
        __syncthreads();
    }
    float mask = e * (1.f / red[0]);
    sc[tid] = mask;
    outA[((size_t)b * PP + tid) * NSTEP + t] = mask;
    __syncthreads();

    const int c = tid & (CC - 1);
    const int half = tid >> 7;
    const __half* cfb = cf + (size_t)b * PP * CC;
    float a = 0.f;
    for (int p = half * 128; p < half * 128 + 128; p++)
        a += sc[p] * __half2float(cfb[(size_t)p * CC + c]);
    red[tid] = a;
    __syncthreads();
    if (tid < CC) att[(size_t)b * CC + tid] = red[tid] + red[tid + 128];
}

__global__ __launch_bounds__(256) void zero2(float* a, float* b) {
    int i = blockIdx.x * 256 + threadIdx.x;
    a[i] = 0.f;
    b[i] = 0.f;
}

__global__ __launch_bounds__(256) void cvt_half(
    const float* __restrict__ src, __half* __restrict__ dst, int n)
{
    int i = blockIdx.x * 256 + threadIdx.x;
    if (i < n) dst[i] = __float2half(src[i]);
}

// ---------------------------- host launcher -------------------------------
extern "C" void kernel_launch(void* const* d_in, const int* in_sizes, int n_in,
                              void* d_out, int out_size)
{
    const float* word_embs = (const float*)d_in[0];
    const float* t_feat    = (const float*)d_in[1];
    const float* c_feats   = (const float*)d_in[2];
    const int o = n_in - 20;
    const float* W_td1 = (const float*)d_in[o + 0];
    const float* W_td2 = (const float*)d_in[o + 1];
    const float* W_td3 = (const float*)d_in[o + 2];
    const float* W_td  = (const float*)d_in[o + 3];
    const float* W1_ih = (const float*)d_in[o + 4];
    const float* W1_hh = (const float*)d_in[o + 5];
    const float* b1_ih = (const float*)d_in[o + 6];
    const float* b1_hh = (const float*)d_in[o + 7];
    const float* W_feat = (const float*)d_in[o + 8];
    const float* W_hidd = (const float*)d_in[o + 9];
    const float* W_att  = (const float*)d_in[o + 10];
    const float* W_l1 = (const float*)d_in[o + 11];
    const float* W_l2 = (const float*)d_in[o + 12];
    const float* W_l  = (const float*)d_in[o + 13];
    const float* W2_ih = (const float*)d_in[o + 14];
    const float* W2_hh = (const float*)d_in[o + 15];
    const float* b2_ih = (const float*)d_in[o + 16];
    const float* b2_hh = (const float*)d_in[o + 17];
    const float* W_cls = (const float*)d_in[o + 18];
    const float* b_cls = (const float*)d_in[o + 19];

    float* out_lang = (float*)d_out;                         // (B, 31, V)
    float* out_att  = out_lang + (size_t)BB * NSTEP * VV;    // (B, P, 31)

    __half *fp16, *cf16;
    float *tdt, *h1a, *h1b, *h2a, *h2b, *tmp, *s, *gx, *gh, *u, *att;
    cudaGetSymbolAddress((void**)&fp16, g_fp16);
    cudaGetSymbolAddress((void**)&cf16, g_cf16);
    cudaGetSymbolAddress((void**)&tdt, g_tdt);
    cudaGetSymbolAddress((void**)&h1a, g_h1a);
    cudaGetSymbolAddress((void**)&h1b, g_h1b);
    cudaGetSymbolAddress((void**)&h2a, g_h2a);
    cudaGetSymbolAddress((void**)&h2b, g_h2b);
    cudaGetSymbolAddress((void**)&tmp, g_tmp);
    cudaGetSymbolAddress((void**)&s,   g_s);
    cudaGetSymbolAddress((void**)&gx,  g_gx);
    cudaGetSymbolAddress((void**)&gh,  g_gh);
    cudaGetSymbolAddress((void**)&u,   g_u);
    cudaGetSymbolAddress((void**)&att, g_att);

    // ---------- prologue ----------
    zero2<<<(BB * HH) / 256, 256>>>(h1a, h2a);
    cvt_half<<<(BB * PP * CC) / 256, 256>>>(c_feats, cf16, BB * PP * CC);
    // td_t = t_feat @ W_td2^T   (256 x 128, K=128)
    gemmv<0><<<dim3(2, 4), 256>>>(
        CC, CC, 0, t_feat, CC, nullptr, 0, W_td2, CC, nullptr, 0,
        nullptr, nullptr, tdt, nullptr, CC);
    // feat_proj = c_feats @ W_feat^T -> fp16  (65536 x 512, K=128)
    gemmv<3><<<dim3(8, 1024), 256>>>(
        HH, CC, 0, c_feats, CC, nullptr, 0, W_feat, CC, nullptr, 0,
        nullptr, nullptr, nullptr, fp16, HH);

    for (int t = 0; t < NSTEP; t++) {
        const float* h1p = (t & 1) ? h1b : h1a;
        float*       h1n = (t & 1) ? h1a : h1b;
        const float* h2p = (t & 1) ? h2b : h2a;
        float*       h2n = (t & 1) ? h2a : h2b;

        // tmp = tanh(x_t@W_td3^T + h2p@W_td1^T + tdt)   dual-source K=300+512
        gemmv<2><<<dim3(2, 4), 256>>>(
            CC, EE, HH, word_embs + (size_t)t * EE, 32 * EE, h2p, HH,
            W_td3, EE, W_td1, HH, nullptr, tdt, tmp, nullptr, CC);
        // s = relu(tmp @ W_td^T)
        gemmv<1><<<dim3(2, 4), 256>>>(
            CC, CC, 0, tmp, CC, nullptr, 0, W_td, CC, nullptr, 0,
            nullptr, nullptr, s, nullptr, CC);
        // GRU1: gx = s@W1_ih^T + b1_ih ; gh = h1p@W1_hh^T + b1_hh
        gemmv<0><<<dim3(24, 4), 256>>>(
            G3H, CC, 0, s, CC, nullptr, 0, W1_ih, CC, nullptr, 0,
            b1_ih, nullptr, gx, nullptr, G3H);
        gemmv<0><<<dim3(24, 4), 256>>>(
            G3H, HH, 0, h1p, HH, nullptr, 0, W1_hh, HH, nullptr, 0,
            b1_hh, nullptr, gh, nullptr, G3H);
        gru_pw<<<(BB * HH) / 256, 256>>>(gx, gh, h1p, h1n);
        // u = h1 @ W_hidd^T
        gemmv<0><<<dim3(8, 4), 256>>>(
            HH, HH, 0, h1n, HH, nullptr, 0, W_hidd, HH, nullptr, 0,
            nullptr, nullptr, u, nullptr, HH);
        // attention
        attn_kernel<<<BB, 256>>>(fp16, u, W_att, cf16, att, out_att, t);
        // tmp = tanh(att@W_l1^T + h1@W_l2^T)   dual-source K=128+512
        gemmv<2><<<dim3(2, 4), 256>>>(
            CC, CC, HH, att, CC, h1n, HH,
            W_l1, CC, W_l2, HH, nullptr, nullptr, tmp, nullptr, CC);
        // s = relu(tmp @ W_l^T)
        gemmv<1><<<dim3(2, 4), 256>>>(
            CC, CC, 0, tmp, CC, nullptr, 0, W_l, CC, nullptr, 0,
            nullptr, nullptr, s, nullptr, CC);
        // GRU2
        gemmv<0><<<dim3(24, 4), 256>>>(
            G3H, CC, 0, s, CC, nullptr, 0, W2_ih, CC, nullptr, 0,
            b2_ih, nullptr, gx, nullptr, G3H);
        gemmv<0><<<dim3(24, 4), 256>>>(
            G3H, HH, 0, h2p, HH, nullptr, 0, W2_hh, HH, nullptr, 0,
            b2_hh, nullptr, gh, nullptr, G3H);
        gru_pw<<<(BB * HH) / 256, 256>>>(gx, gh, h2p, h2n);
        // logits = h2 @ W_cls^T + b_cls -> out_lang[:, t, :]
        gemmv<0><<<dim3((VV + 63) / 64, 4), 256>>>(
            VV, HH, 0, h2n, HH, nullptr, 0, W_cls, HH, nullptr, 0,
            b_cls, nullptr, out_lang + (size_t)t * VV, nullptr, NSTEP * VV);
    }
}